// round 6
// baseline (speedup 1.0000x reference)
#include <cuda_runtime.h>
#include <cstdint>

// NODE forest: B=1048576, 64 inputs, 8 trees x depth 6, TREE_DIM=2.
// R6: R5 design (sample-pair f32x2 lanes, mov-free inner loop) with fixes:
//  - W inner-loop loads are LDS.64 (stride-65 u64 rows are 8B-aligned only;
//    the R5 ulonglong2 LDS.128 was the misaligned-address crash)
//  - x transpose staged with feature-dependent column rotation (slot = P + i4)
//    -> conflict-free shared writes AND reads, unpadded 128-u64 stride
//  - 256 threads, smem 94592 B -> 2 blocks/SM = 4 warps/SMSP (R4 lesson:
//    2 warps/SMSP exposes LDS latency; keep 4)
//
// Numerics (bit-faithful): ascending-i single FMA chain per (sample,selector),
// bias AFTER dot, bit = fl(0.5 + 0.25*z) > 0.5 (XLA logistic rounding).

#define THREADS 256
#define SPB 256
#define NBLK 4096

// ---- shared layout ----
// Wd  : u64[48][65] = 24960 @ 0       (W duplicated (w,w), row stride 65 u64)
// xt  : u64[64][128] = 65536 @ 24960  (xt[i][(P + (i>>2)) & 127] = {x[2P][i], x[2P+1][i]})
// tbl : float2[512]  = 4096 @ 90496
#define WD_OFF   0
#define XT_OFF   24960
#define TBL_OFF  90496
#define SMEM_BYTES 94592

static __device__ __forceinline__ unsigned long long pack2f(float lo, float hi) {
    unsigned long long r;
    asm("mov.b64 %0, {%1, %2};" : "=l"(r) : "f"(lo), "f"(hi));
    return r;
}
static __device__ __forceinline__ void unpack2f(unsigned long long v, float& lo, float& hi) {
    asm("mov.b64 {%0, %1}, %2;" : "=f"(lo), "=f"(hi) : "l"(v));
}
static __device__ __forceinline__ void ffma2(unsigned long long& d,
                                             unsigned long long a,
                                             unsigned long long b) {
    asm("fma.rn.f32x2 %0, %1, %2, %0;" : "+l"(d) : "l"(a), "l"(b));
}
static __device__ __forceinline__ void fadd2(unsigned long long& d,
                                             unsigned long long a) {
    asm("add.rn.f32x2 %0, %0, %1;" : "+l"(d) : "l"(a));
}
static __device__ __forceinline__ int xla_bit(float z) {
    return __fadd_rn(0.5f, __fmul_rn(0.25f, z)) > 0.5f;
}

__global__ __launch_bounds__(THREADS, 2)
void node_forest_kernel(const float*  __restrict__ x,      // [B,64]
                        const float*  __restrict__ Wsel,   // [48,64]
                        const float*  __restrict__ bsel,   // [48]
                        const float*  __restrict__ leafv,  // [8,64,2]
                        const float*  __restrict__ fcw,    // [2,16]
                        const float*  __restrict__ fcb,    // [2]
                        float2*       __restrict__ out)    // [B] float2
{
    extern __shared__ unsigned char smem[];
    unsigned long long* Wd  = (unsigned long long*)(smem + WD_OFF);
    unsigned long long* xt  = (unsigned long long*)(smem + XT_OFF);
    float*              xtf = (float*)(smem + XT_OFF);
    float2*             tbl = (float2*)(smem + TBL_OFF);

    const int tid = threadIdx.x;

    // ---- stage W duplicated: Wd[d*65 + i] = (w, w) ----
    #pragma unroll
    for (int e = tid; e < 3072; e += THREADS) {
        int d = e >> 6, i = e & 63;
        float w = Wsel[e];
        Wd[d * 65 + i] = pack2f(w, w);
    }

    // ---- stage x transposed with rotation: feature f -> slot (P + f>>2) & 127 ----
    // word addr = f*256 + slot*2 + half; banks = 2*((P + c) mod 16) + half
    // -> 32 distinct banks per warp (conflict-free writes)
    const float4* xg = (const float4*)x + (size_t)blockIdx.x * (SPB * 16);
    #pragma unroll
    for (int it = 0; it < 16; ++it) {
        int f4 = tid + it * THREADS;     // float4 index in tile (0..4095)
        float4 v = xg[f4];
        int s = f4 >> 4;                 // sample 0..255
        int c = f4 & 15;                 // float4 column = feature>>2
        int P = s >> 1, half = s & 1;
        int slot = (P + c) & 127;
        float* dst = xtf + (4 * c) * 256 + slot * 2 + half;
        dst[0]   = v.x;
        dst[256] = v.y;
        dst[512] = v.z;
        dst[768] = v.w;
    }

    // ---- fold leaf_values with fc_w ----
    #pragma unroll
    for (int e = tid; e < 512; e += THREADS) {
        int t = e >> 6, leaf = e & 63;
        float l0 = leafv[t * 128 + leaf * 2 + 0];
        float l1 = leafv[t * 128 + leaf * 2 + 1];
        tbl[e] = make_float2(l0 * fcw[t * 2]      + l1 * fcw[t * 2 + 1],
                             l0 * fcw[16 + t * 2] + l1 * fcw[16 + t * 2 + 1]);
    }
    __syncthreads();

    const int gq = tid & 3;      // trees 2gq, 2gq+1 -> selectors 12gq..12gq+11
    const int sg = tid >> 2;     // 0..63; sample pairs P = jp*64 + sg
    const int D0 = 12 * gq;

    unsigned long long acc[12][2];
    #pragma unroll
    for (int d = 0; d < 12; ++d) { acc[d][0] = 0ull; acc[d][1] = 0ull; }

    const unsigned long long* wbase = Wd + D0 * 65;

    #pragma unroll 2
    for (int i4 = 0; i4 < 16; ++i4) {
        const int i = i4 * 4;
        const int s0 = (sg + i4) & 127;        // rotated slot, jp=0
        const int s1 = (64 + sg + i4) & 127;   // rotated slot, jp=1

        // x sample-pairs: 4 features x 2 pairs, direct LDS.64 (consecutive addrs)
        unsigned long long xd[4][2];
        #pragma unroll
        for (int k = 0; k < 4; ++k) {
            xd[k][0] = xt[(i + k) * 128 + s0];
            xd[k][1] = xt[(i + k) * 128 + s1];
        }
        #pragma unroll
        for (int d = 0; d < 12; ++d) {
            const unsigned long long* wr = wbase + d * 65 + i;
            unsigned long long w0 = wr[0];
            unsigned long long w1 = wr[1];
            unsigned long long w2 = wr[2];
            unsigned long long w3 = wr[3];
            #pragma unroll
            for (int jp = 0; jp < 2; ++jp) {
                ffma2(acc[d][jp], w0, xd[0][jp]);
                ffma2(acc[d][jp], w1, xd[1][jp]);
                ffma2(acc[d][jp], w2, xd[2][jp]);
                ffma2(acc[d][jp], w3, xd[3][jp]);
            }
        }
    }

    // ---- bias (after dot), bits -> leaf idx -> folded-table gather ----
    #pragma unroll
    for (int d = 0; d < 12; ++d) {
        float b = __ldg(&bsel[D0 + d]);
        unsigned long long b2 = pack2f(b, b);
        fadd2(acc[d][0], b2);
        fadd2(acc[d][1], b2);
    }

    const float fb0 = __ldg(&fcb[0]), fb1 = __ldg(&fcb[1]);
    float4 res[2];
    #pragma unroll
    for (int jp = 0; jp < 2; ++jp) {
        int lAe = 0, lAo = 0, lBe = 0, lBo = 0;
        #pragma unroll
        for (int d = 0; d < 6; ++d) {
            float l, h;
            unpack2f(acc[d][jp], l, h);          // tree 2gq, depth d
            if (xla_bit(l)) lAe |= (32 >> d);
            if (xla_bit(h)) lAo |= (32 >> d);
            unpack2f(acc[d + 6][jp], l, h);      // tree 2gq+1, depth d
            if (xla_bit(l)) lBe |= (32 >> d);
            if (xla_bit(h)) lBo |= (32 >> d);
        }
        float2 tae = tbl[(2 * gq) * 64 + lAe];
        float2 tbe = tbl[(2 * gq + 1) * 64 + lBe];
        float2 tao = tbl[(2 * gq) * 64 + lAo];
        float2 tbo = tbl[(2 * gq + 1) * 64 + lBo];
        float e0 = tae.x + tbe.x, e1 = tae.y + tbe.y;
        float o0 = tao.x + tbo.x, o1 = tao.y + tbo.y;
        // reduce over the 4 gq lanes (lane bits 0-1)
        e0 += __shfl_xor_sync(0xffffffffu, e0, 1);
        e1 += __shfl_xor_sync(0xffffffffu, e1, 1);
        o0 += __shfl_xor_sync(0xffffffffu, o0, 1);
        o1 += __shfl_xor_sync(0xffffffffu, o1, 1);
        e0 += __shfl_xor_sync(0xffffffffu, e0, 2);
        e1 += __shfl_xor_sync(0xffffffffu, e1, 2);
        o0 += __shfl_xor_sync(0xffffffffu, o0, 2);
        o1 += __shfl_xor_sync(0xffffffffu, o1, 2);
        res[jp] = make_float4(e0 + fb0, e1 + fb1, o0 + fb0, o1 + fb1);
    }
    // lanes gq=0,1 store pair P = gq*64 + sg as one float4 (samples 2P, 2P+1)
    if (gq < 2) {
        ((float4*)out)[(size_t)blockIdx.x * 128 + gq * 64 + sg] = res[gq];
    }
}

extern "C" void kernel_launch(void* const* d_in, const int* in_sizes, int n_in,
                              void* d_out, int out_size) {
    (void)in_sizes; (void)n_in; (void)out_size;
    cudaFuncSetAttribute(node_forest_kernel,
                         cudaFuncAttributeMaxDynamicSharedMemorySize, SMEM_BYTES);
    cudaFuncSetAttribute(node_forest_kernel,
                         cudaFuncAttributePreferredSharedMemoryCarveout, 100);
    node_forest_kernel<<<NBLK, THREADS, SMEM_BYTES>>>(
        (const float*)d_in[0],   // x
        (const float*)d_in[1],   // W_sel
        (const float*)d_in[2],   // b_sel
        (const float*)d_in[3],   // leaf_values
        (const float*)d_in[4],   // fc_w
        (const float*)d_in[5],   // fc_b
        (float2*)d_out);
}

// round 7
// speedup vs baseline: 1.2678x; 1.2678x over previous
#include <cuda_runtime.h>
#include <cstdint>

// NODE forest: B=1048576, 64 inputs, 8 trees x depth 6, TREE_DIM=2.
// R7: per-tree sample-pair tiling.
//   thread = (tree gq in 0..7, sample-group sg in 0..15)
//   per thread: 16 samples (8 f32x2 pairs) x 6 depth-selectors of ONE tree
//   acc[6][8] u64 = 96 regs; x loaded as u64 sample-pairs (no movs);
//   W loaded scalar (4B/lane) + 1 dup-mov; bytes/FFMA2 = 1.83.
//
// Numerics (bit-faithful): ascending-i single FMA chain per (sample,selector),
// bias AFTER dot, bit = fl(0.5 + 0.25*z) > 0.5 (XLA logistic rounding).

#define THREADS 128
#define SPB 256          // samples per block (128 pairs)
#define NBLK 4096

// ---- shared layout ----
// Wf  : f32[48][66] = 12672 @ 0      (scalar W, stride 66 -> 8 tree rows on distinct banks)
// xt  : u64[64][128] = 65536 @ 12672 (xt[i][(P + (i>>2)) & 127] = {x[2P][i], x[2P+1][i]})
// tbl : float2[512]  = 4096 @ 78208
#define WF_OFF   0
#define XT_OFF   12672
#define TBL_OFF  78208
#define SMEM_BYTES 82304

static __device__ __forceinline__ unsigned long long pack2f(float lo, float hi) {
    unsigned long long r;
    asm("mov.b64 %0, {%1, %2};" : "=l"(r) : "f"(lo), "f"(hi));
    return r;
}
static __device__ __forceinline__ void unpack2f(unsigned long long v, float& lo, float& hi) {
    asm("mov.b64 {%0, %1}, %2;" : "=f"(lo), "=f"(hi) : "l"(v));
}
static __device__ __forceinline__ void ffma2(unsigned long long& d,
                                             unsigned long long a,
                                             unsigned long long b) {
    asm("fma.rn.f32x2 %0, %1, %2, %0;" : "+l"(d) : "l"(a), "l"(b));
}
static __device__ __forceinline__ void fadd2(unsigned long long& d,
                                             unsigned long long a) {
    asm("add.rn.f32x2 %0, %0, %1;" : "+l"(d) : "l"(a));
}
static __device__ __forceinline__ int xla_bit(float z) {
    return __fadd_rn(0.5f, __fmul_rn(0.25f, z)) > 0.5f;
}

__global__ __launch_bounds__(THREADS, 2)
void node_forest_kernel(const float*  __restrict__ x,      // [B,64]
                        const float*  __restrict__ Wsel,   // [48,64]
                        const float*  __restrict__ bsel,   // [48]
                        const float*  __restrict__ leafv,  // [8,64,2]
                        const float*  __restrict__ fcw,    // [2,16]
                        const float*  __restrict__ fcb,    // [2]
                        float2*       __restrict__ out)    // [B] float2
{
    extern __shared__ unsigned char smem[];
    float*              Wf  = (float*)(smem + WF_OFF);
    unsigned long long* xt  = (unsigned long long*)(smem + XT_OFF);
    float*              xtf = (float*)(smem + XT_OFF);
    float2*             tbl = (float2*)(smem + TBL_OFF);

    const int tid = threadIdx.x;

    // ---- stage W scalar, stride 66 (tree rows -> distinct banks) ----
    #pragma unroll
    for (int e = tid; e < 3072; e += THREADS) {
        int d = e >> 6, i = e & 63;
        Wf[d * 66 + i] = Wsel[e];
    }

    // ---- stage x transposed with rotation: feature f -> slot (P + f>>2) & 127 ----
    const float4* xg = (const float4*)x + (size_t)blockIdx.x * (SPB * 16);
    #pragma unroll
    for (int it = 0; it < 32; ++it) {
        int f4 = tid + it * THREADS;     // float4 index in tile (0..4095)
        float4 v = xg[f4];
        int s = f4 >> 4;                 // sample 0..255
        int c = f4 & 15;                 // float4 column = feature>>2
        int P = s >> 1, half = s & 1;
        int slot = (P + c) & 127;
        float* dst = xtf + (4 * c) * 256 + slot * 2 + half;
        dst[0]   = v.x;
        dst[256] = v.y;
        dst[512] = v.z;
        dst[768] = v.w;
    }

    // ---- fold leaf_values with fc_w ----
    #pragma unroll
    for (int e = tid; e < 512; e += THREADS) {
        int t = e >> 6, leaf = e & 63;
        float l0 = leafv[t * 128 + leaf * 2 + 0];
        float l1 = leafv[t * 128 + leaf * 2 + 1];
        tbl[e] = make_float2(l0 * fcw[t * 2]      + l1 * fcw[t * 2 + 1],
                             l0 * fcw[16 + t * 2] + l1 * fcw[16 + t * 2 + 1]);
    }
    __syncthreads();

    const int gq = tid & 7;      // tree index; selectors gq*6 .. gq*6+5
    const int sg = tid >> 3;     // 0..15; pairs sg*8 .. sg*8+7 (16 samples)
    const float* wrow = Wf + gq * 6 * 66;

    unsigned long long acc[6][8];
    #pragma unroll
    for (int d = 0; d < 6; ++d)
        #pragma unroll
        for (int p = 0; p < 8; ++p) acc[d][p] = 0ull;

    #pragma unroll 2
    for (int i4 = 0; i4 < 16; ++i4) {
        const int i = i4 * 4;
        const int sbase = sg * 8 + i4;   // rotated slot base for this thread

        #pragma unroll
        for (int k = 0; k < 4; ++k) {
            // x sample-pairs: 8 direct u64 loads (consecutive slots, wraps at 128)
            unsigned long long xd[8];
            #pragma unroll
            for (int p = 0; p < 8; ++p)
                xd[p] = xt[(i + k) * 128 + ((sbase + p) & 127)];
            // W scalars for the 6 depths of this tree at feature i+k
            #pragma unroll
            for (int d = 0; d < 6; ++d) {
                float w = wrow[d * 66 + i + k];
                unsigned long long w2 = pack2f(w, w);
                #pragma unroll
                for (int p = 0; p < 8; ++p) ffma2(acc[d][p], w2, xd[p]);
            }
        }
    }

    // ---- bias (after dot) ----
    #pragma unroll
    for (int d = 0; d < 6; ++d) {
        float b = __ldg(&bsel[gq * 6 + d]);
        unsigned long long b2 = pack2f(b, b);
        #pragma unroll
        for (int p = 0; p < 8; ++p) fadd2(acc[d][p], b2);
    }

    // ---- bits -> leaf idx -> per-tree folded-table gather ----
    const float fb0 = __ldg(&fcb[0]), fb1 = __ldg(&fcb[1]);
    const float2* trow = tbl + gq * 64;

    float4 res[8];
    #pragma unroll
    for (int p = 0; p < 8; ++p) {
        int le = 0, lo = 0;              // leaves for samples 2P (even) and 2P+1 (odd)
        #pragma unroll
        for (int d = 0; d < 6; ++d) {
            float zl, zh;
            unpack2f(acc[d][p], zl, zh);
            if (xla_bit(zl)) le |= (32 >> d);
            if (xla_bit(zh)) lo |= (32 >> d);
        }
        float2 te = trow[le];
        float2 to = trow[lo];
        float e0 = te.x, e1 = te.y, o0 = to.x, o1 = to.y;
        // reduce over the 8 tree lanes (lane bits 0-2)
        #pragma unroll
        for (int m = 1; m < 8; m <<= 1) {
            e0 += __shfl_xor_sync(0xffffffffu, e0, m);
            e1 += __shfl_xor_sync(0xffffffffu, e1, m);
            o0 += __shfl_xor_sync(0xffffffffu, o0, m);
            o1 += __shfl_xor_sync(0xffffffffu, o1, m);
        }
        res[p] = make_float4(e0 + fb0, e1 + fb1, o0 + fb0, o1 + fb1);
    }
    // lane (sg,gq) stores pair index sg*8 + gq -> float4 index == tid (coalesced)
    ((float4*)out)[(size_t)blockIdx.x * 128 + tid] = res[gq];
}

extern "C" void kernel_launch(void* const* d_in, const int* in_sizes, int n_in,
                              void* d_out, int out_size) {
    (void)in_sizes; (void)n_in; (void)out_size;
    cudaFuncSetAttribute(node_forest_kernel,
                         cudaFuncAttributeMaxDynamicSharedMemorySize, SMEM_BYTES);
    cudaFuncSetAttribute(node_forest_kernel,
                         cudaFuncAttributePreferredSharedMemoryCarveout, 100);
    node_forest_kernel<<<NBLK, THREADS, SMEM_BYTES>>>(
        (const float*)d_in[0],   // x
        (const float*)d_in[1],   // W_sel
        (const float*)d_in[2],   // b_sel
        (const float*)d_in[3],   // leaf_values
        (const float*)d_in[4],   // fc_w
        (const float*)d_in[5],   // fc_b
        (float2*)d_out);
}